// round 12
// baseline (speedup 1.0000x reference)
#include <cuda_runtime.h>
#include <cuda_bf16.h>

#define NB 8
#define NPTS 16384
#define NQ 1024
#define NC 64
#define NS 32
#define R2 0.04f

// 2 MB scratch: xyz packed as float4 for single-LDG.128 scan loads.
__device__ float4 g_xyz4[(size_t)NB * NPTS];
// 33.5 MB scratch: features transposed to (B, N, C); fits in L2 (126 MB).
__device__ float g_feats_t[(size_t)NB * NPTS * NC];
// completion counters for in-grid pipelining
__device__ int g_pack_done;
__device__ int g_trans_done;

#define PACK_BLOCKS  ((NB * NPTS) / 128)   // 1024
#define TRANS_BLOCKS (NB * (NPTS / 32))    // 4096
#define QAG_BLOCKS   (NB * NQ)             // 8192
#define FSTRIDE 68   // fsm row stride in floats: conflict-free STS.128/LDS.128

__global__ void reset_kernel() { g_pack_done = 0; g_trans_done = 0; }

struct QagSmem {
    int   idx_buf[NS + 1024];   // 31 carried + <=1024 appended: unchecked stores
    int   wtot[2][4];           // double-buffered per-warp counts
    float fsm[NS * FSTRIDE];    // [sample][channel]
};
union SmemU {
    QagSmem q;
    float   tile[32][65];       // transpose tile
    float   sbuf[4][96];        // pack staging
};

__global__ __launch_bounds__(128) void fused_kernel(
    const float* __restrict__ xyz,      // (B, N, 3)
    const float* __restrict__ feats,    // (B, C, N)
    const float* __restrict__ new_xyz,  // (B, S, 3)
    float* __restrict__ out)            // (B, 3+C, S, NS)
{
    __shared__ SmemU sm;
    const int bid = blockIdx.x;

    if (bid < PACK_BLOCKS) {
        // ---- pack (B,N,3) -> float4: 4 warps x 32 points ----
        const int warp = threadIdx.x >> 5, lane = threadIdx.x & 31;
        const size_t base = (size_t)bid * 128 + warp * 32;
        const float* src = xyz + base * 3;
        float* s = &sm.sbuf[warp][0];
        s[lane]      = src[lane];
        s[lane + 32] = src[lane + 32];
        s[lane + 64] = src[lane + 64];
        __syncwarp();
        g_xyz4[base + lane] = make_float4(s[lane * 3], s[lane * 3 + 1], s[lane * 3 + 2], 0.f);
        __threadfence();
        __syncthreads();
        if (threadIdx.x == 0) atomicAdd(&g_pack_done, 1);

    } else if (bid < PACK_BLOCKS + TRANS_BLOCKS) {
        // ---- transpose (B,C,N) -> (B,N,C): one 32n x 64c tile, 128 threads ----
        const int tb = bid - PACK_BLOCKS;
        const int b  = tb >> 9;                  // / (NPTS/32)
        const int n0 = (tb & 511) * 32;
        const int t  = threadIdx.x;
        const int tx = t & 31;                   // n within tile
        const int ty = t >> 5;                   // 0..3

        const float* src = feats + (size_t)b * NC * NPTS + n0;
        #pragma unroll
        for (int k = 0; k < 16; ++k) {
            const int c = ty * 16 + k;
            sm.tile[tx][c] = src[(size_t)c * NPTS + tx];
        }
        __syncthreads();

        float* dst = g_feats_t + ((size_t)b * NPTS + n0) * NC;
        #pragma unroll
        for (int k = 0; k < 16; ++k) {
            const int idx = k * 128 + t;
            const int n = idx >> 6;
            const int c = idx & 63;
            dst[(size_t)n * NC + c] = sm.tile[n][c];
        }
        __threadfence();
        __syncthreads();
        if (threadIdx.x == 0) atomicAdd(&g_trans_done, 1);

    } else {
        // ---- qag: one block (4 warps) per query (R8 body + pipeline waits) ----
        const int lane = threadIdx.x & 31;
        const int w    = threadIdx.x >> 5;
        const int q = bid - PACK_BLOCKS - TRANS_BLOCKS;
        const int b = q >> 10;
        const int s = q & (NQ - 1);

        const float qx = new_xyz[q * 3 + 0];
        const float qy = new_xyz[q * 3 + 1];
        const float qz = new_xyz[q * 3 + 2];

        // wait: xyz pack complete
        if (threadIdx.x == 0) {
            while (atomicAdd(&g_pack_done, 0) < PACK_BLOCKS) __nanosleep(256);
        }
        __syncthreads();
        __threadfence();

        const float4* __restrict__ xb4 = g_xyz4 + (size_t)b * NPTS;
        const unsigned lt = (1u << lane) - 1u;

        int cnt = 0;
        int pb = 0;
        for (int j0 = 0; j0 < NPTS; j0 += 1024) {
            const int jw = j0 + w * 256;
            float4 p[8];
            #pragma unroll
            for (int u = 0; u < 8; ++u) p[u] = xb4[jw + u * 32 + lane];

            bool wi[8];
            #pragma unroll
            for (int u = 0; u < 8; ++u) {
                const float dx = p[u].x - qx;
                const float dy = p[u].y - qy;
                const float dz = p[u].z - qz;
                wi[u] = dx * dx + dy * dy + dz * dz < R2;
            }
            unsigned m[8];
            #pragma unroll
            for (int u = 0; u < 8; ++u) m[u] = __ballot_sync(0xFFFFFFFFu, wi[u]);

            int tot = 0;
            #pragma unroll
            for (int u = 0; u < 8; ++u) tot += __popc(m[u]);
            if (lane == 0) sm.q.wtot[pb][w] = tot;
            __syncthreads();

            int base = cnt;
            #pragma unroll
            for (int ww = 0; ww < 4; ++ww) {
                const int t = sm.q.wtot[pb][ww];
                if (ww < w) base += t;
                cnt += t;
            }
            #pragma unroll
            for (int u = 0; u < 8; ++u) {
                if (wi[u]) sm.q.idx_buf[base + __popc(m[u] & lt)] = jw + u * 32 + lane;
                base += __popc(m[u]);
            }
            pb ^= 1;
            if (cnt >= NS) break;   // uniform across block
        }
        __syncthreads();            // final-round idx_buf visible

        const int eff = cnt < NS ? cnt : NS;
        const int first = (eff > 0) ? sm.q.idx_buf[0] : 0;

        const size_t CH = (size_t)NQ * NS;
        float* ob = out + ((size_t)b * (3 + NC) * NQ + s) * NS + lane;

        // grouped xyz (needs only pack) — before the transpose wait
        if (w == 0) {
            const int im = (lane < eff) ? sm.q.idx_buf[lane] : first;
            const float4 P = xb4[im];
            ob[0 * CH] = P.x - qx;
            ob[1 * CH] = P.y - qy;
            ob[2 * CH] = P.z - qz;
        }

        // wait: feature transpose complete
        if (threadIdx.x == 0) {
            while (atomicAdd(&g_trans_done, 0) < TRANS_BLOCKS) __nanosleep(1024);
        }
        __syncthreads();
        __threadfence();

        // grouped features: half-warp per sample row -> fsm via STS.128
        {
            const float4* __restrict__ fbase =
                (const float4*)(g_feats_t + (size_t)b * NPTS * NC);
            const int g    = lane & 15;
            const int half = lane >> 4;
            #pragma unroll
            for (int i = 0; i < 4; ++i) {
                const int msamp = 8 * w + 2 * i + half;
                const int im = (msamp < eff) ? sm.q.idx_buf[msamp] : first;
                const float4 v = __ldg(fbase + (size_t)im * (NC / 4) + g);
                *(float4*)&sm.q.fsm[msamp * FSTRIDE + 4 * g] = v;
            }
        }
        __syncthreads();

        // writeout: warp w covers channels 16w..16w+15 via LDS.128, lane = sample
        float* of = ob + 3 * CH;
        #pragma unroll
        for (int c4 = 0; c4 < 4; ++c4) {
            const int ch0 = 16 * w + 4 * c4;
            const float4 fv = *(const float4*)&sm.q.fsm[lane * FSTRIDE + ch0];
            of[(size_t)(ch0 + 0) * CH] = fv.x;
            of[(size_t)(ch0 + 1) * CH] = fv.y;
            of[(size_t)(ch0 + 2) * CH] = fv.z;
            of[(size_t)(ch0 + 3) * CH] = fv.w;
        }
    }
}

extern "C" void kernel_launch(void* const* d_in, const int* in_sizes, int n_in,
                              void* d_out, int out_size) {
    const float* xyz     = (const float*)d_in[0];
    const float* new_xyz = (const float*)d_in[1];
    const float* feats   = (const float*)d_in[2];
    float* out = (float*)d_out;

    reset_kernel<<<1, 1>>>();
    fused_kernel<<<PACK_BLOCKS + TRANS_BLOCKS + QAG_BLOCKS, 128>>>(
        xyz, feats, new_xyz, out);
}